// round 2
// baseline (speedup 1.0000x reference)
#include <cuda_runtime.h>
#include <cuda_bf16.h>
#include <math.h>

// Problem constants
#define BB 2
#define LL 2048
#define DD 2048
#define NN 16
#define KX 96          // DT_RANK + 2*D_STATE
#define NCH 32         // chunks along L
#define CH 64          // chunk length (NCH*CH == LL)

typedef unsigned long long u64;

// ---------------- scratch (device globals) ----------------
__device__ __align__(16) float g_xpart[4][BB * LL * KX];    // gemm1 K-split partials (6 MB)
__device__ __align__(16) float g_xdbl[BB * LL * KX];        // 1.5 MB
__device__ __align__(16) float g_dt[BB * LL * DD];          // 33.5 MB
__device__ __align__(16) float g_hf[BB * NCH * DD * NN];    // 8.4 MB
__device__ __align__(16) float g_h0[BB * NCH * DD * NN];    // 8.4 MB
__device__ __align__(16) float g_sdt[BB * NCH * DD];        // 0.5 MB

// ---------------- f32x2 helpers ----------------
__device__ __forceinline__ u64 pk2(float lo, float hi) {
    u64 r; asm("mov.b64 %0,{%1,%2};" : "=l"(r) : "f"(lo), "f"(hi)); return r;
}
__device__ __forceinline__ void unpk2(u64 v, float& lo, float& hi) {
    asm("mov.b64 {%0,%1},%2;" : "=f"(lo), "=f"(hi) : "l"(v));
}
__device__ __forceinline__ u64 fma2(u64 a, u64 b, u64 c) {
    u64 d; asm("fma.rn.f32x2 %0,%1,%2,%3;" : "=l"(d) : "l"(a), "l"(b), "l"(c)); return d;
}
__device__ __forceinline__ u64 mul2(u64 a, u64 b) {
    u64 d; asm("mul.rn.f32x2 %0,%1,%2;" : "=l"(d) : "l"(a), "l"(b)); return d;
}

// ================= GEMM1 (K-split x4): partial[s][r][k] = sum_{d in slice} u[r][d]*W_x[k][d] =====
// M=4096 rows, N=96, per-block K-slice=512. 512 blocks. Tile 32 rows x 96 cols,
// micro-tile 4 rows x 3 cols, row-pair packed f32x2 accumulators, pre-packed W pairs.
__global__ void __launch_bounds__(256) k_gemm1(const float* __restrict__ u,
                                               const float* __restrict__ Wx) {
    __shared__ __align__(16) u64 us2[32][17];   // [k][row-pair] packed {r0,r1}
    __shared__ __align__(16) u64 ws2[32][97];   // [k][col] packed {w,w}
    const int r0 = blockIdx.x * 32;
    const int ks = blockIdx.y;                  // K-slice 0..3
    const int kbeg = ks * 512;
    const int tid = threadIdx.x;
    const int tx = tid & 31, ty = tid >> 5;

    u64 acc[2][3];
#pragma unroll
    for (int i = 0; i < 2; i++)
#pragma unroll
        for (int j = 0; j < 3; j++) acc[i][j] = 0ull;

    for (int k0 = kbeg; k0 < kbeg + 512; k0 += 32) {
        __syncthreads();
        {
            const int kk = tid & 31;
            const int base = tid >> 5;
#pragma unroll
            for (int p = 0; p < 2; p++) {
                int rp = base + p * 8;
                float v0 = u[(size_t)(r0 + 2 * rp) * 2048 + k0 + kk];
                float v1 = u[(size_t)(r0 + 2 * rp + 1) * 2048 + k0 + kk];
                us2[kk][rp] = pk2(v0, v1);
            }
#pragma unroll
            for (int p = 0; p < 12; p++) {
                int c = base + p * 8;
                float w = Wx[(size_t)c * 2048 + k0 + kk];
                ws2[kk][c] = pk2(w, w);
            }
        }
        __syncthreads();
#pragma unroll
        for (int k = 0; k < 32; k++) {
            u64 ua = us2[k][ty * 2];
            u64 ub = us2[k][ty * 2 + 1];
#pragma unroll
            for (int j = 0; j < 3; j++) {
                u64 w2 = ws2[k][tx * 3 + j];
                acc[0][j] = fma2(ua, w2, acc[0][j]);
                acc[1][j] = fma2(ub, w2, acc[1][j]);
            }
        }
    }
    float* dst = g_xpart[ks];
#pragma unroll
    for (int i = 0; i < 2; i++)
#pragma unroll
        for (int j = 0; j < 3; j++) {
            float lo, hi; unpk2(acc[i][j], lo, hi);
            int row = r0 + ty * 4 + 2 * i;
            int col = tx * 3 + j;
            dst[row * KX + col] = lo;
            dst[(row + 1) * KX + col] = hi;
        }
}

// ================= reduce the 4 partials (deterministic) =================
__global__ void __launch_bounds__(256) k_red1() {
    int idx = blockIdx.x * 256 + threadIdx.x;        // float4 index, < 98304
    const float4* p0 = (const float4*)g_xpart[0];
    const float4* p1 = (const float4*)g_xpart[1];
    const float4* p2 = (const float4*)g_xpart[2];
    const float4* p3 = (const float4*)g_xpart[3];
    float4 a = p0[idx], b = p1[idx], c = p2[idx], d = p3[idx];
    float4 r;
    r.x = (a.x + b.x) + (c.x + d.x);
    r.y = (a.y + b.y) + (c.y + d.y);
    r.z = (a.z + b.z) + (c.z + d.z);
    r.w = (a.w + b.w) + (c.w + d.w);
    ((float4*)g_xdbl)[idx] = r;
}

// ========= GEMM2: dt[r][d] = softplus(sum_k dtraw[r][k]*W_dt[d][k] + b_dt[d]) =========
__global__ void __launch_bounds__(256) k_gemm2(const float* __restrict__ Wdt,
                                               const float* __restrict__ bdt) {
    __shared__ __align__(16) u64   us2[64][17];
    __shared__ __align__(16) float ws[64][132];
    const int r0 = blockIdx.x * 32;
    const int c0 = blockIdx.y * 128;
    const int tid = threadIdx.x;
    const int tx = tid & 31, ty = tid >> 5;

#pragma unroll
    for (int p = 0; p < 4; p++) {
        int idx = tid + p * 256;
        int k = idx & 63, rp = idx >> 6;
        float v0 = g_xdbl[(r0 + 2 * rp) * KX + k];
        float v1 = g_xdbl[(r0 + 2 * rp + 1) * KX + k];
        us2[k][rp] = pk2(v0, v1);
    }
#pragma unroll
    for (int p = 0; p < 32; p++) {
        int idx = tid + p * 256;
        int k = idx & 63, c = idx >> 6;
        ws[k][c] = Wdt[(size_t)(c0 + c) * 64 + k];
    }
    __syncthreads();

    u64 acc[2][4];
#pragma unroll
    for (int i = 0; i < 2; i++)
#pragma unroll
        for (int j = 0; j < 4; j++) acc[i][j] = 0ull;

#pragma unroll 16
    for (int k = 0; k < 64; k++) {
        u64 ua = us2[k][ty * 2];
        u64 ub = us2[k][ty * 2 + 1];
        float4 w4 = *(const float4*)&ws[k][tx * 4];
        float wv[4] = {w4.x, w4.y, w4.z, w4.w};
#pragma unroll
        for (int j = 0; j < 4; j++) {
            u64 w2 = pk2(wv[j], wv[j]);
            acc[0][j] = fma2(ua, w2, acc[0][j]);
            acc[1][j] = fma2(ub, w2, acc[1][j]);
        }
    }

    float bb[4];
#pragma unroll
    for (int j = 0; j < 4; j++) bb[j] = bdt[c0 + tx * 4 + j];

#pragma unroll
    for (int i = 0; i < 2; i++)
#pragma unroll
        for (int j = 0; j < 4; j++) {
            float lo, hi; unpk2(acc[i][j], lo, hi);
            int row = r0 + ty * 4 + 2 * i;
            int col = c0 + tx * 4 + j;
            float x0 = lo + bb[j];
            float x1 = hi + bb[j];
            float s0 = fmaxf(x0, 0.f) + __logf(1.f + __expf(-fabsf(x0)));
            float s1 = fmaxf(x1, 0.f) + __logf(1.f + __expf(-fabsf(x1)));
            g_dt[(size_t)row * DD + col] = s0;
            g_dt[(size_t)(row + 1) * DD + col] = s1;
        }
}

// ---------------- per-thread A setup + structure check ----------------
__device__ __forceinline__ bool load_A(const float* __restrict__ A_log, int d, float Av[16]) {
#pragma unroll
    for (int n = 0; n < 16; n += 4) {
        float4 a4 = *(const float4*)&A_log[d * 16 + n];
        Av[n]     = -__expf(a4.x);
        Av[n + 1] = -__expf(a4.y);
        Av[n + 2] = -__expf(a4.z);
        Av[n + 3] = -__expf(a4.w);
    }
    bool ok = (Av[0] < 0.f);
#pragma unroll
    for (int n = 1; n < 16; n++) {
        float tgt = (float)(n + 1) * Av[0];
        ok = ok && (fabsf(Av[n] - tgt) <= 4e-6f * fabsf(tgt));
    }
    return ok;
}

// Log-depth power pairs: p[q] = (e1^{2q+1}, e1^{2q+2})
__device__ __forceinline__ void pow_tree(float e1, u64 p[8]) {
    float e2 = e1 * e1;
    float e4 = e2 * e2;
    float e8 = e4 * e4;
    u64 e2p = pk2(e2, e2), e4p = pk2(e4, e4), e8p = pk2(e8, e8);
    p[0] = pk2(e1, e2);
    p[1] = mul2(p[0], e2p);
    p[2] = mul2(p[0], e4p);
    p[3] = mul2(p[1], e4p);
    p[4] = mul2(p[0], e8p);
    p[5] = mul2(p[1], e8p);
    p[6] = mul2(p[2], e8p);
    p[7] = mul2(p[3], e8p);
}

// ================= Scan phase A: local scan per chunk from h=0 =================
__global__ void __launch_bounds__(256) k_scanA(const float* __restrict__ u,
                                               const float* __restrict__ A_log) {
    __shared__ __align__(16) float sB[CH][16];
    const int b = blockIdx.z, c = blockIdx.y;
    const int tid = threadIdx.x;
    const int d = blockIdx.x * 256 + tid;
    const int l0 = c * CH;

#pragma unroll
    for (int p = 0; p < 4; p++) {
        int idx = tid + p * 256;
        int t = idx >> 4, j = idx & 15;
        sB[t][j] = g_xdbl[(b * LL + l0 + t) * KX + 64 + j];
    }
    __syncthreads();

    float Av[16];
    bool powok = load_A(A_log, d, Av);

    u64 h2[8];
#pragma unroll
    for (int p = 0; p < 8; p++) h2[p] = 0ull;
    float sdt = 0.f;

    const size_t base0 = (size_t)(b * LL + l0) * DD + d;
    const float* dtp = g_dt + base0;
    const float* up = u + base0;

    float dtv[2][8], uv[2][8];
#pragma unroll
    for (int j = 0; j < 8; j++) { dtv[0][j] = dtp[(size_t)j * DD]; uv[0][j] = up[(size_t)j * DD]; }

    if (powok) {
        const float A0 = Av[0];
#pragma unroll
        for (int g = 0; g < 8; g++) {
            const int cur = g & 1, nxt = cur ^ 1;
            if (g < 7) {
#pragma unroll
                for (int j = 0; j < 8; j++) {
                    dtv[nxt][j] = dtp[(size_t)((g + 1) * 8 + j) * DD];
                    uv[nxt][j]  = up[(size_t)((g + 1) * 8 + j) * DD];
                }
            }
#pragma unroll
            for (int j = 0; j < 8; j++) {
                const int t = g * 8 + j;
                float dt = dtv[cur][j], uu = uv[cur][j];
                sdt += dt;
                u64 pw[8]; pow_tree(__expf(A0 * dt), pw);
                float dtu = dt * uu;
                u64 dtu2 = pk2(dtu, dtu);
#pragma unroll
                for (int p = 0; p < 8; p++) {
                    u64 B2 = *(const u64*)&sB[t][2 * p];
                    h2[p] = fma2(pw[p], h2[p], mul2(dtu2, B2));
                }
            }
        }
    } else {
#pragma unroll
        for (int g = 0; g < 8; g++) {
            const int cur = g & 1, nxt = cur ^ 1;
            if (g < 7) {
#pragma unroll
                for (int j = 0; j < 8; j++) {
                    dtv[nxt][j] = dtp[(size_t)((g + 1) * 8 + j) * DD];
                    uv[nxt][j]  = up[(size_t)((g + 1) * 8 + j) * DD];
                }
            }
#pragma unroll
            for (int j = 0; j < 8; j++) {
                const int t = g * 8 + j;
                float dt = dtv[cur][j], uu = uv[cur][j];
                sdt += dt;
                float dtu = dt * uu;
                u64 dtu2 = pk2(dtu, dtu);
#pragma unroll
                for (int p = 0; p < 8; p++) {
                    u64 a2 = pk2(__expf(dt * Av[2 * p]), __expf(dt * Av[2 * p + 1]));
                    u64 B2 = *(const u64*)&sB[t][2 * p];
                    h2[p] = fma2(a2, h2[p], mul2(dtu2, B2));
                }
            }
        }
    }

    u64* hf = (u64*)(g_hf + ((size_t)((b * NCH + c) * DD) + d) * NN);
#pragma unroll
    for (int p = 0; p < 8; p++) hf[p] = h2[p];
    g_sdt[(b * NCH + c) * DD + d] = sdt;
}

// ================= Scan phase B: inter-chunk recurrence (fully preloaded) =================
__global__ void __launch_bounds__(256) k_scanB(const float* __restrict__ A_log) {
    const int gid = blockIdx.x * 256 + threadIdx.x;  // < B*D*N = 65536
    const int b = gid >> 15;
    const int rem = gid & 32767;
    const int d = rem >> 4;
    const int n = rem & 15;
    const float A = -__expf(A_log[d * 16 + n]);

    float av[NCH], fv[NCH];
#pragma unroll
    for (int c = 0; c < NCH; c++) {
        int base = (b * NCH + c) * DD + d;
        av[c] = g_sdt[base];
        fv[c] = g_hf[(size_t)base * NN + n];
    }
#pragma unroll
    for (int c = 0; c < NCH; c++) av[c] = __expf(A * av[c]);

    float h = 0.f;
#pragma unroll
    for (int c = 0; c < NCH; c++) {
        int base = (b * NCH + c) * DD + d;
        g_h0[(size_t)base * NN + n] = h;
        h = fmaf(av[c], h, fv[c]);
    }
}

// ================= Scan phase C: re-scan with correct h0, emit y =================
__global__ void __launch_bounds__(256) k_scanC(const float* __restrict__ u,
                                               const float* __restrict__ A_log,
                                               const float* __restrict__ Dv,
                                               float* __restrict__ out) {
    __shared__ __align__(16) float sBC[CH][32];
    const int b = blockIdx.z, c = blockIdx.y;
    const int tid = threadIdx.x;
    const int d = blockIdx.x * 256 + tid;
    const int l0 = c * CH;

#pragma unroll
    for (int p = 0; p < 8; p++) {
        int idx = tid + p * 256;
        int t = idx >> 5, j = idx & 31;
        sBC[t][j] = g_xdbl[(b * LL + l0 + t) * KX + 64 + j];
    }
    __syncthreads();

    float Av[16];
    bool powok = load_A(A_log, d, Av);
    const float Dd = Dv[d];

    u64 h2[8];
    {
        const u64* h0p = (const u64*)(g_h0 + ((size_t)((b * NCH + c) * DD) + d) * NN);
#pragma unroll
        for (int p = 0; p < 8; p++) h2[p] = h0p[p];
    }

    const size_t base0 = (size_t)(b * LL + l0) * DD + d;
    const float* dtp = g_dt + base0;
    const float* up = u + base0;
    float* yp = out + base0;

    float dtv[2][8], uv[2][8];
#pragma unroll
    for (int j = 0; j < 8; j++) { dtv[0][j] = dtp[(size_t)j * DD]; uv[0][j] = up[(size_t)j * DD]; }

    if (powok) {
        const float A0 = Av[0];
#pragma unroll
        for (int g = 0; g < 8; g++) {
            const int cur = g & 1, nxt = cur ^ 1;
            if (g < 7) {
#pragma unroll
                for (int j = 0; j < 8; j++) {
                    dtv[nxt][j] = dtp[(size_t)((g + 1) * 8 + j) * DD];
                    uv[nxt][j]  = up[(size_t)((g + 1) * 8 + j) * DD];
                }
            }
#pragma unroll
            for (int j = 0; j < 8; j++) {
                const int t = g * 8 + j;
                float dt = dtv[cur][j], uu = uv[cur][j];
                u64 pw[8]; pow_tree(__expf(A0 * dt), pw);
                float dtu = dt * uu;
                u64 dtu2 = pk2(dtu, dtu);
                u64 y2 = 0ull;
#pragma unroll
                for (int p = 0; p < 8; p++) {
                    u64 B2 = *(const u64*)&sBC[t][2 * p];
                    u64 C2 = *(const u64*)&sBC[t][16 + 2 * p];
                    h2[p] = fma2(pw[p], h2[p], mul2(dtu2, B2));
                    y2 = fma2(h2[p], C2, y2);
                }
                float ylo, yhi; unpk2(y2, ylo, yhi);
                yp[(size_t)t * DD] = fmaf(uu, Dd, ylo + yhi);
            }
        }
    } else {
#pragma unroll
        for (int g = 0; g < 8; g++) {
            const int cur = g & 1, nxt = cur ^ 1;
            if (g < 7) {
#pragma unroll
                for (int j = 0; j < 8; j++) {
                    dtv[nxt][j] = dtp[(size_t)((g + 1) * 8 + j) * DD];
                    uv[nxt][j]  = up[(size_t)((g + 1) * 8 + j) * DD];
                }
            }
#pragma unroll
            for (int j = 0; j < 8; j++) {
                const int t = g * 8 + j;
                float dt = dtv[cur][j], uu = uv[cur][j];
                float dtu = dt * uu;
                u64 dtu2 = pk2(dtu, dtu);
                u64 y2 = 0ull;
#pragma unroll
                for (int p = 0; p < 8; p++) {
                    u64 a2 = pk2(__expf(dt * Av[2 * p]), __expf(dt * Av[2 * p + 1]));
                    u64 B2 = *(const u64*)&sBC[t][2 * p];
                    u64 C2 = *(const u64*)&sBC[t][16 + 2 * p];
                    h2[p] = fma2(a2, h2[p], mul2(dtu2, B2));
                    y2 = fma2(h2[p], C2, y2);
                }
                float ylo, yhi; unpk2(y2, ylo, yhi);
                yp[(size_t)t * DD] = fmaf(uu, Dd, ylo + yhi);
            }
        }
    }
}

// ================= launch =================
extern "C" void kernel_launch(void* const* d_in, const int* in_sizes, int n_in,
                              void* d_out, int out_size) {
    const float* u     = (const float*)d_in[0];
    const float* A_log = (const float*)d_in[1];
    const float* Dv    = (const float*)d_in[2];
    const float* Wx    = (const float*)d_in[3];
    const float* Wdt   = (const float*)d_in[4];
    const float* bdt   = (const float*)d_in[5];
    float* out = (float*)d_out;

    k_gemm1<<<dim3(128, 4), 256>>>(u, Wx);
    k_red1<<<384, 256>>>();
    k_gemm2<<<dim3(128, 16), 256>>>(Wdt, bdt);
    k_scanA<<<dim3(DD / 256, NCH, BB), 256>>>(u, A_log);
    k_scanB<<<(BB * DD * NN) / 256, 256>>>(A_log);
    k_scanC<<<dim3(DD / 256, NCH, BB), 256>>>(u, A_log, Dv, out);
}

// round 3
// speedup vs baseline: 1.3351x; 1.3351x over previous
#include <cuda_runtime.h>
#include <cuda_bf16.h>
#include <math.h>

// Problem constants
#define BB 2
#define LL 2048
#define DD 2048
#define NN 16
#define KX 96          // DT_RANK + 2*D_STATE
#define NCH 32         // chunks along L
#define CH 64          // chunk length (NCH*CH == LL)

typedef unsigned long long u64;

// ---------------- scratch (device globals) ----------------
__device__ __align__(16) float g_xpart[4][BB * LL * KX];    // gemm1 K-split partials (6 MB)
__device__ __align__(16) float g_xdbl[BB * LL * KX];        // 1.5 MB
__device__ __align__(16) float g_dt[BB * LL * DD];          // 33.5 MB
__device__ __align__(16) float g_hf[BB * NCH * DD * NN];    // 8.4 MB
__device__ __align__(16) float g_h0[BB * NCH * DD * NN];    // 8.4 MB
__device__ __align__(16) float g_sdt[BB * NCH * DD];        // 0.5 MB

// ---------------- f32x2 helpers ----------------
__device__ __forceinline__ u64 pk2(float lo, float hi) {
    u64 r; asm("mov.b64 %0,{%1,%2};" : "=l"(r) : "f"(lo), "f"(hi)); return r;
}
__device__ __forceinline__ void unpk2(u64 v, float& lo, float& hi) {
    asm("mov.b64 {%0,%1},%2;" : "=f"(lo), "=f"(hi) : "l"(v));
}
__device__ __forceinline__ u64 fma2(u64 a, u64 b, u64 c) {
    u64 d; asm("fma.rn.f32x2 %0,%1,%2,%3;" : "=l"(d) : "l"(a), "l"(b), "l"(c)); return d;
}
__device__ __forceinline__ u64 mul2(u64 a, u64 b) {
    u64 d; asm("mul.rn.f32x2 %0,%1,%2;" : "=l"(d) : "l"(a), "l"(b)); return d;
}

// ================= GEMM1 (K-split x4) =================
__global__ void __launch_bounds__(256) k_gemm1(const float* __restrict__ u,
                                               const float* __restrict__ Wx) {
    __shared__ __align__(16) u64 us2[32][17];   // [k][row-pair] packed {r0,r1}
    __shared__ __align__(16) u64 ws2[32][97];   // [k][col] packed {w,w}
    const int r0 = blockIdx.x * 32;
    const int ks = blockIdx.y;                  // K-slice 0..3
    const int kbeg = ks * 512;
    const int tid = threadIdx.x;
    const int tx = tid & 31, ty = tid >> 5;

    u64 acc[2][3];
#pragma unroll
    for (int i = 0; i < 2; i++)
#pragma unroll
        for (int j = 0; j < 3; j++) acc[i][j] = 0ull;

    for (int k0 = kbeg; k0 < kbeg + 512; k0 += 32) {
        __syncthreads();
        {
            const int kk = tid & 31;
            const int base = tid >> 5;
#pragma unroll
            for (int p = 0; p < 2; p++) {
                int rp = base + p * 8;
                float v0 = u[(size_t)(r0 + 2 * rp) * 2048 + k0 + kk];
                float v1 = u[(size_t)(r0 + 2 * rp + 1) * 2048 + k0 + kk];
                us2[kk][rp] = pk2(v0, v1);
            }
#pragma unroll
            for (int p = 0; p < 12; p++) {
                int c = base + p * 8;
                float w = Wx[(size_t)c * 2048 + k0 + kk];
                ws2[kk][c] = pk2(w, w);
            }
        }
        __syncthreads();
#pragma unroll
        for (int k = 0; k < 32; k++) {
            u64 ua = us2[k][ty * 2];
            u64 ub = us2[k][ty * 2 + 1];
#pragma unroll
            for (int j = 0; j < 3; j++) {
                u64 w2 = ws2[k][tx * 3 + j];
                acc[0][j] = fma2(ua, w2, acc[0][j]);
                acc[1][j] = fma2(ub, w2, acc[1][j]);
            }
        }
    }
    float* dst = g_xpart[ks];
#pragma unroll
    for (int i = 0; i < 2; i++)
#pragma unroll
        for (int j = 0; j < 3; j++) {
            float lo, hi; unpk2(acc[i][j], lo, hi);
            int row = r0 + ty * 4 + 2 * i;
            int col = tx * 3 + j;
            dst[row * KX + col] = lo;
            dst[(row + 1) * KX + col] = hi;
        }
}

// ================= reduce the 4 partials (deterministic) =================
__global__ void __launch_bounds__(256) k_red1() {
    int idx = blockIdx.x * 256 + threadIdx.x;        // float4 index, < 98304
    const float4* p0 = (const float4*)g_xpart[0];
    const float4* p1 = (const float4*)g_xpart[1];
    const float4* p2 = (const float4*)g_xpart[2];
    const float4* p3 = (const float4*)g_xpart[3];
    float4 a = p0[idx], b = p1[idx], c = p2[idx], d = p3[idx];
    float4 r;
    r.x = (a.x + b.x) + (c.x + d.x);
    r.y = (a.y + b.y) + (c.y + d.y);
    r.z = (a.z + b.z) + (c.z + d.z);
    r.w = (a.w + b.w) + (c.w + d.w);
    ((float4*)g_xdbl)[idx] = r;
}

// ========= GEMM2: dt[r][d] = softplus(dtraw@W_dt^T + b_dt) =========
__global__ void __launch_bounds__(256) k_gemm2(const float* __restrict__ Wdt,
                                               const float* __restrict__ bdt) {
    __shared__ __align__(16) u64   us2[64][17];
    __shared__ __align__(16) float ws[64][132];
    const int r0 = blockIdx.x * 32;
    const int c0 = blockIdx.y * 128;
    const int tid = threadIdx.x;
    const int tx = tid & 31, ty = tid >> 5;

#pragma unroll
    for (int p = 0; p < 4; p++) {
        int idx = tid + p * 256;
        int k = idx & 63, rp = idx >> 6;
        float v0 = g_xdbl[(r0 + 2 * rp) * KX + k];
        float v1 = g_xdbl[(r0 + 2 * rp + 1) * KX + k];
        us2[k][rp] = pk2(v0, v1);
    }
#pragma unroll
    for (int p = 0; p < 32; p++) {
        int idx = tid + p * 256;
        int k = idx & 63, c = idx >> 6;
        ws[k][c] = Wdt[(size_t)(c0 + c) * 64 + k];
    }
    __syncthreads();

    u64 acc[2][4];
#pragma unroll
    for (int i = 0; i < 2; i++)
#pragma unroll
        for (int j = 0; j < 4; j++) acc[i][j] = 0ull;

#pragma unroll 16
    for (int k = 0; k < 64; k++) {
        u64 ua = us2[k][ty * 2];
        u64 ub = us2[k][ty * 2 + 1];
        float4 w4 = *(const float4*)&ws[k][tx * 4];
        float wv[4] = {w4.x, w4.y, w4.z, w4.w};
#pragma unroll
        for (int j = 0; j < 4; j++) {
            u64 w2 = pk2(wv[j], wv[j]);
            acc[0][j] = fma2(ua, w2, acc[0][j]);
            acc[1][j] = fma2(ub, w2, acc[1][j]);
        }
    }

    float bb[4];
#pragma unroll
    for (int j = 0; j < 4; j++) bb[j] = bdt[c0 + tx * 4 + j];

#pragma unroll
    for (int i = 0; i < 2; i++)
#pragma unroll
        for (int j = 0; j < 4; j++) {
            float lo, hi; unpk2(acc[i][j], lo, hi);
            int row = r0 + ty * 4 + 2 * i;
            int col = c0 + tx * 4 + j;
            float x0 = lo + bb[j];
            float x1 = hi + bb[j];
            float s0 = fmaxf(x0, 0.f) + __logf(1.f + __expf(-fabsf(x0)));
            float s1 = fmaxf(x1, 0.f) + __logf(1.f + __expf(-fabsf(x1)));
            g_dt[(size_t)row * DD + col] = s0;
            g_dt[(size_t)(row + 1) * DD + col] = s1;
        }
}

// ---------------- per-thread A setup + structure check ----------------
__device__ __forceinline__ bool load_A(const float* __restrict__ A_log, int d, float Av[16]) {
#pragma unroll
    for (int n = 0; n < 16; n += 4) {
        float4 a4 = *(const float4*)&A_log[d * 16 + n];
        Av[n]     = -__expf(a4.x);
        Av[n + 1] = -__expf(a4.y);
        Av[n + 2] = -__expf(a4.z);
        Av[n + 3] = -__expf(a4.w);
    }
    bool ok = (Av[0] < 0.f);
#pragma unroll
    for (int n = 1; n < 16; n++) {
        float tgt = (float)(n + 1) * Av[0];
        ok = ok && (fabsf(Av[n] - tgt) <= 4e-6f * fabsf(tgt));
    }
    return ok;
}

// ================= Scan phase A: local scan per chunk from h=0 =================
// Lean body: serial power chain, no manual prefetch buffers (occupancy hides latency).
__global__ void __launch_bounds__(256) k_scanA(const float* __restrict__ u,
                                               const float* __restrict__ A_log) {
    __shared__ __align__(16) float sB[CH][16];
    const int b = blockIdx.z, c = blockIdx.y;
    const int tid = threadIdx.x;
    const int d = blockIdx.x * 256 + tid;
    const int l0 = c * CH;

#pragma unroll
    for (int p = 0; p < 4; p++) {
        int idx = tid + p * 256;
        int t = idx >> 4, j = idx & 15;
        sB[t][j] = g_xdbl[(b * LL + l0 + t) * KX + 64 + j];
    }
    __syncthreads();

    float Av[16];
    const bool powok = load_A(A_log, d, Av);

    u64 h2[8];
#pragma unroll
    for (int p = 0; p < 8; p++) h2[p] = 0ull;
    float sdt = 0.f;

    const size_t base0 = (size_t)(b * LL + l0) * DD + d;
    const float* dtp = g_dt + base0;
    const float* up = u + base0;

    if (powok) {
        const float A0 = Av[0];
#pragma unroll 2
        for (int t = 0; t < CH; t++) {
            float dt = __ldg(dtp + (size_t)t * DD);
            float uu = __ldg(up + (size_t)t * DD);
            sdt += dt;
            float e1 = __expf(A0 * dt);
            float e2 = e1 * e1;
            u64 a2 = pk2(e1, e2);
            u64 e22 = pk2(e2, e2);
            float dtu = dt * uu;
            u64 dtu2 = pk2(dtu, dtu);
#pragma unroll
            for (int p = 0; p < 8; p++) {
                u64 B2 = *(const u64*)&sB[t][2 * p];
                h2[p] = fma2(a2, h2[p], mul2(dtu2, B2));
                if (p < 7) a2 = mul2(a2, e22);
            }
        }
    } else {
        for (int t = 0; t < CH; t++) {
            float dt = __ldg(dtp + (size_t)t * DD);
            float uu = __ldg(up + (size_t)t * DD);
            sdt += dt;
            float dtu = dt * uu;
            u64 dtu2 = pk2(dtu, dtu);
#pragma unroll
            for (int p = 0; p < 8; p++) {
                u64 a2 = pk2(__expf(dt * Av[2 * p]), __expf(dt * Av[2 * p + 1]));
                u64 B2 = *(const u64*)&sB[t][2 * p];
                h2[p] = fma2(a2, h2[p], mul2(dtu2, B2));
            }
        }
    }

    u64* hf = (u64*)(g_hf + ((size_t)((b * NCH + c) * DD) + d) * NN);
#pragma unroll
    for (int p = 0; p < 8; p++) hf[p] = h2[p];
    g_sdt[(b * NCH + c) * DD + d] = sdt;
}

// ================= Scan phase B: inter-chunk recurrence (fully preloaded, NCH=32) =================
__global__ void __launch_bounds__(256) k_scanB(const float* __restrict__ A_log) {
    const int gid = blockIdx.x * 256 + threadIdx.x;  // < B*D*N = 65536
    const int b = gid >> 15;
    const int rem = gid & 32767;
    const int d = rem >> 4;
    const int n = rem & 15;
    const float A = -__expf(A_log[d * 16 + n]);

    float av[NCH], fv[NCH];
#pragma unroll
    for (int c = 0; c < NCH; c++) {
        int base = (b * NCH + c) * DD + d;
        av[c] = g_sdt[base];
        fv[c] = g_hf[(size_t)base * NN + n];
    }
#pragma unroll
    for (int c = 0; c < NCH; c++) av[c] = __expf(A * av[c]);

    float h = 0.f;
#pragma unroll
    for (int c = 0; c < NCH; c++) {
        int base = (b * NCH + c) * DD + d;
        g_h0[(size_t)base * NN + n] = h;
        h = fmaf(av[c], h, fv[c]);
    }
}

// ================= Scan phase C: re-scan with correct h0, emit y =================
__global__ void __launch_bounds__(256) k_scanC(const float* __restrict__ u,
                                               const float* __restrict__ A_log,
                                               const float* __restrict__ Dv,
                                               float* __restrict__ out) {
    __shared__ __align__(16) float sBC[CH][32];
    const int b = blockIdx.z, c = blockIdx.y;
    const int tid = threadIdx.x;
    const int d = blockIdx.x * 256 + tid;
    const int l0 = c * CH;

#pragma unroll
    for (int p = 0; p < 8; p++) {
        int idx = tid + p * 256;
        int t = idx >> 5, j = idx & 31;
        sBC[t][j] = g_xdbl[(b * LL + l0 + t) * KX + 64 + j];
    }
    __syncthreads();

    float Av[16];
    const bool powok = load_A(A_log, d, Av);
    const float Dd = Dv[d];

    u64 h2[8];
    {
        const u64* h0p = (const u64*)(g_h0 + ((size_t)((b * NCH + c) * DD) + d) * NN);
#pragma unroll
        for (int p = 0; p < 8; p++) h2[p] = h0p[p];
    }

    const size_t base0 = (size_t)(b * LL + l0) * DD + d;
    const float* dtp = g_dt + base0;
    const float* up = u + base0;
    float* yp = out + base0;

    if (powok) {
        const float A0 = Av[0];
#pragma unroll 2
        for (int t = 0; t < CH; t++) {
            float dt = __ldg(dtp + (size_t)t * DD);
            float uu = __ldg(up + (size_t)t * DD);
            float e1 = __expf(A0 * dt);
            float e2 = e1 * e1;
            u64 a2 = pk2(e1, e2);
            u64 e22 = pk2(e2, e2);
            float dtu = dt * uu;
            u64 dtu2 = pk2(dtu, dtu);
            u64 y2 = 0ull;
#pragma unroll
            for (int p = 0; p < 8; p++) {
                u64 B2 = *(const u64*)&sBC[t][2 * p];
                u64 C2 = *(const u64*)&sBC[t][16 + 2 * p];
                h2[p] = fma2(a2, h2[p], mul2(dtu2, B2));
                y2 = fma2(h2[p], C2, y2);
                if (p < 7) a2 = mul2(a2, e22);
            }
            float ylo, yhi; unpk2(y2, ylo, yhi);
            yp[(size_t)t * DD] = fmaf(uu, Dd, ylo + yhi);
        }
    } else {
        for (int t = 0; t < CH; t++) {
            float dt = __ldg(dtp + (size_t)t * DD);
            float uu = __ldg(up + (size_t)t * DD);
            float dtu = dt * uu;
            u64 dtu2 = pk2(dtu, dtu);
            u64 y2 = 0ull;
#pragma unroll
            for (int p = 0; p < 8; p++) {
                u64 a2 = pk2(__expf(dt * Av[2 * p]), __expf(dt * Av[2 * p + 1]));
                u64 B2 = *(const u64*)&sBC[t][2 * p];
                u64 C2 = *(const u64*)&sBC[t][16 + 2 * p];
                h2[p] = fma2(a2, h2[p], mul2(dtu2, B2));
                y2 = fma2(h2[p], C2, y2);
            }
            float ylo, yhi; unpk2(y2, ylo, yhi);
            yp[(size_t)t * DD] = fmaf(uu, Dd, ylo + yhi);
        }
    }
}

// ================= launch =================
extern "C" void kernel_launch(void* const* d_in, const int* in_sizes, int n_in,
                              void* d_out, int out_size) {
    const float* u     = (const float*)d_in[0];
    const float* A_log = (const float*)d_in[1];
    const float* Dv    = (const float*)d_in[2];
    const float* Wx    = (const float*)d_in[3];
    const float* Wdt   = (const float*)d_in[4];
    const float* bdt   = (const float*)d_in[5];
    float* out = (float*)d_out;

    k_gemm1<<<dim3(128, 4), 256>>>(u, Wx);
    k_red1<<<384, 256>>>();
    k_gemm2<<<dim3(128, 16), 256>>>(Wdt, bdt);
    k_scanA<<<dim3(DD / 256, NCH, BB), 256>>>(u, A_log);
    k_scanB<<<(BB * DD * NN) / 256, 256>>>(A_log);
    k_scanC<<<dim3(DD / 256, NCH, BB), 256>>>(u, A_log, Dv, out);
}

// round 4
// speedup vs baseline: 1.4987x; 1.1225x over previous
#include <cuda_runtime.h>
#include <cuda_bf16.h>
#include <math.h>

// Problem constants
#define BB 2
#define LL 2048
#define DD 2048
#define NN 16
#define KX 96          // DT_RANK + 2*D_STATE
#define NCH 64         // chunks along L
#define CH 32          // chunk length (NCH*CH == LL)

typedef unsigned long long u64;

// ---------------- scratch (device globals) ----------------
__device__ __align__(16) float g_xpart[8][BB * LL * KX];    // gemm1 K-split partials (12 MB)
__device__ __align__(16) float g_xdbl[BB * LL * KX];        // 1.5 MB
__device__ __align__(16) float g_dt[BB * LL * DD];          // 33.5 MB
__device__ __align__(16) float g_hf[BB * NCH * DD * NN];    // 16.8 MB
__device__ __align__(16) float g_h0[BB * NCH * DD * NN];    // 16.8 MB
__device__ __align__(16) float g_sdt[BB * NCH * DD];        // 1 MB

// ---------------- f32x2 helpers ----------------
__device__ __forceinline__ u64 pk2(float lo, float hi) {
    u64 r; asm("mov.b64 %0,{%1,%2};" : "=l"(r) : "f"(lo), "f"(hi)); return r;
}
__device__ __forceinline__ void unpk2(u64 v, float& lo, float& hi) {
    asm("mov.b64 {%0,%1},%2;" : "=f"(lo), "=f"(hi) : "l"(v));
}
__device__ __forceinline__ u64 fma2(u64 a, u64 b, u64 c) {
    u64 d; asm("fma.rn.f32x2 %0,%1,%2,%3;" : "=l"(d) : "l"(a), "l"(b), "l"(c)); return d;
}
__device__ __forceinline__ u64 mul2(u64 a, u64 b) {
    u64 d; asm("mul.rn.f32x2 %0,%1,%2;" : "=l"(d) : "l"(a), "l"(b)); return d;
}

// ================= GEMM1 (K-split x8): 64-row tiles, micro 4rp x 3c =================
__global__ void __launch_bounds__(256) k_gemm1(const float* __restrict__ u,
                                               const float* __restrict__ Wx) {
    __shared__ __align__(16) u64 us2[32][32];   // [k][row-pair] packed {r0,r1} (broadcast reads)
    __shared__ __align__(16) u64 ws2[32][97];   // [k][col] packed {w,w}
    const int r0 = blockIdx.x * 64;
    const int kbeg = blockIdx.y * 256;          // K-slice of 256
    const int tid = threadIdx.x;
    const int tx = tid & 31, ty = tid >> 5;

    u64 acc[4][3];
#pragma unroll
    for (int i = 0; i < 4; i++)
#pragma unroll
        for (int j = 0; j < 3; j++) acc[i][j] = 0ull;

    for (int k0 = kbeg; k0 < kbeg + 256; k0 += 32) {
        __syncthreads();
        {   // stage u: 32 row-pairs x 32 k (one float4-group per thread)
            const int rp = tid >> 3;
            const int kq = (tid & 7) * 4;
            const float4 a0 = *(const float4*)&u[(size_t)(r0 + 2 * rp) * 2048 + k0 + kq];
            const float4 a1 = *(const float4*)&u[(size_t)(r0 + 2 * rp + 1) * 2048 + k0 + kq];
            us2[kq + 0][rp] = pk2(a0.x, a1.x);
            us2[kq + 1][rp] = pk2(a0.y, a1.y);
            us2[kq + 2][rp] = pk2(a0.z, a1.z);
            us2[kq + 3][rp] = pk2(a0.w, a1.w);
            // stage W: 96 cols x 32 k
#pragma unroll
            for (int p = 0; p < 3; p++) {
                int g = tid + p * 256;
                int c = g >> 3;
                int kw = (g & 7) * 4;
                float4 w = *(const float4*)&Wx[(size_t)c * 2048 + k0 + kw];
                ws2[kw + 0][c] = pk2(w.x, w.x);
                ws2[kw + 1][c] = pk2(w.y, w.y);
                ws2[kw + 2][c] = pk2(w.z, w.z);
                ws2[kw + 3][c] = pk2(w.w, w.w);
            }
        }
        __syncthreads();
#pragma unroll
        for (int k = 0; k < 32; k++) {
            u64 ua[4];
#pragma unroll
            for (int i = 0; i < 4; i++) ua[i] = us2[k][ty * 4 + i];
#pragma unroll
            for (int j = 0; j < 3; j++) {
                u64 w2 = ws2[k][tx * 3 + j];
#pragma unroll
                for (int i = 0; i < 4; i++) acc[i][j] = fma2(ua[i], w2, acc[i][j]);
            }
        }
    }
    float* dst = g_xpart[blockIdx.y];
#pragma unroll
    for (int i = 0; i < 4; i++)
#pragma unroll
        for (int j = 0; j < 3; j++) {
            float lo, hi; unpk2(acc[i][j], lo, hi);
            int row = r0 + ty * 8 + 2 * i;
            int col = tx * 3 + j;
            dst[row * KX + col] = lo;
            dst[(row + 1) * KX + col] = hi;
        }
}

// ================= reduce the 8 partials (deterministic) =================
__global__ void __launch_bounds__(256) k_red1() {
    int idx = blockIdx.x * 256 + threadIdx.x;        // float4 index, < 98304
    float4 s = ((const float4*)g_xpart[0])[idx];
#pragma unroll
    for (int p = 1; p < 8; p++) {
        float4 a = ((const float4*)g_xpart[p])[idx];
        s.x += a.x; s.y += a.y; s.z += a.z; s.w += a.w;
    }
    ((float4*)g_xdbl)[idx] = s;
}

// ========= GEMM2: 64x128 tile, micro 4rp x 4c =========
__global__ void __launch_bounds__(256) k_gemm2(const float* __restrict__ Wdt,
                                               const float* __restrict__ bdt) {
    __shared__ __align__(16) u64   us2[64][32];   // 16 KB (broadcast reads)
    __shared__ __align__(16) float ws[64][128];   // 32 KB
    const int r0 = blockIdx.x * 64;
    const int c0 = blockIdx.y * 128;
    const int tid = threadIdx.x;
    const int tx = tid & 31, ty = tid >> 5;

#pragma unroll
    for (int p = 0; p < 2; p++) {
        int g = tid + p * 256;
        int rp = g >> 4;           // 0..31
        int kq = (g & 15) * 4;     // 0..60
        const float4 a0 = *(const float4*)&g_xdbl[(r0 + 2 * rp) * KX + kq];
        const float4 a1 = *(const float4*)&g_xdbl[(r0 + 2 * rp + 1) * KX + kq];
        us2[kq + 0][rp] = pk2(a0.x, a1.x);
        us2[kq + 1][rp] = pk2(a0.y, a1.y);
        us2[kq + 2][rp] = pk2(a0.z, a1.z);
        us2[kq + 3][rp] = pk2(a0.w, a1.w);
    }
#pragma unroll
    for (int p = 0; p < 8; p++) {
        int g = tid + p * 256;
        int c = g & 127;
        int kq = (g >> 7) * 4;
        float4 w = *(const float4*)&Wdt[(size_t)(c0 + c) * 64 + kq];
        ws[kq + 0][c] = w.x;
        ws[kq + 1][c] = w.y;
        ws[kq + 2][c] = w.z;
        ws[kq + 3][c] = w.w;
    }
    __syncthreads();

    u64 acc[4][4];
#pragma unroll
    for (int i = 0; i < 4; i++)
#pragma unroll
        for (int j = 0; j < 4; j++) acc[i][j] = 0ull;

#pragma unroll 8
    for (int k = 0; k < 64; k++) {
        u64 ua[4];
#pragma unroll
        for (int i = 0; i < 4; i++) ua[i] = us2[k][ty * 4 + i];
        float4 w4 = *(const float4*)&ws[k][tx * 4];
        u64 w2[4] = {pk2(w4.x, w4.x), pk2(w4.y, w4.y), pk2(w4.z, w4.z), pk2(w4.w, w4.w)};
#pragma unroll
        for (int j = 0; j < 4; j++)
#pragma unroll
            for (int i = 0; i < 4; i++) acc[i][j] = fma2(ua[i], w2[j], acc[i][j]);
    }

    float bb[4];
#pragma unroll
    for (int j = 0; j < 4; j++) bb[j] = bdt[c0 + tx * 4 + j];

#pragma unroll
    for (int i = 0; i < 4; i++)
#pragma unroll
        for (int j = 0; j < 4; j++) {
            float lo, hi; unpk2(acc[i][j], lo, hi);
            int row = r0 + ty * 8 + 2 * i;
            int col = c0 + tx * 4 + j;
            float x0 = lo + bb[j];
            float x1 = hi + bb[j];
            float s0 = fmaxf(x0, 0.f) + __logf(1.f + __expf(-fabsf(x0)));
            float s1 = fmaxf(x1, 0.f) + __logf(1.f + __expf(-fabsf(x1)));
            g_dt[(size_t)row * DD + col] = s0;
            g_dt[(size_t)(row + 1) * DD + col] = s1;
        }
}

// ---------------- per-thread A setup + structure check ----------------
__device__ __forceinline__ bool load_A(const float* __restrict__ A_log, int d, float Av[16]) {
#pragma unroll
    for (int n = 0; n < 16; n += 4) {
        float4 a4 = *(const float4*)&A_log[d * 16 + n];
        Av[n]     = -__expf(a4.x);
        Av[n + 1] = -__expf(a4.y);
        Av[n + 2] = -__expf(a4.z);
        Av[n + 3] = -__expf(a4.w);
    }
    bool ok = (Av[0] < 0.f);
#pragma unroll
    for (int n = 1; n < 16; n++) {
        float tgt = (float)(n + 1) * Av[0];
        ok = ok && (fabsf(Av[n] - tgt) <= 4e-6f * fabsf(tgt));
    }
    return ok;
}

// ================= Scan phase A: local scan per chunk from h=0 =================
__global__ void __launch_bounds__(256) k_scanA(const float* __restrict__ u,
                                               const float* __restrict__ A_log) {
    __shared__ __align__(16) float sB[CH][16];
    const int b = blockIdx.z, c = blockIdx.y;
    const int tid = threadIdx.x;
    const int d = blockIdx.x * 256 + tid;
    const int l0 = c * CH;

#pragma unroll
    for (int p = 0; p < 2; p++) {
        int idx = tid + p * 256;
        int t = idx >> 4, j = idx & 15;
        sB[t][j] = g_xdbl[(b * LL + l0 + t) * KX + 64 + j];
    }
    __syncthreads();

    float Av[16];
    const bool powok = load_A(A_log, d, Av);

    u64 h2[8];
#pragma unroll
    for (int p = 0; p < 8; p++) h2[p] = 0ull;
    float sdt = 0.f;

    const size_t base0 = (size_t)(b * LL + l0) * DD + d;
    const float* dtp = g_dt + base0;
    const float* up = u + base0;

    if (powok) {
        const float A0 = Av[0];
#pragma unroll 2
        for (int t = 0; t < CH; t++) {
            float dt = __ldg(dtp + (size_t)t * DD);
            float uu = __ldg(up + (size_t)t * DD);
            sdt += dt;
            float e1 = __expf(A0 * dt);
            float e2 = e1 * e1;
            u64 a2 = pk2(e1, e2);
            u64 e22 = pk2(e2, e2);
            float dtu = dt * uu;
            u64 dtu2 = pk2(dtu, dtu);
#pragma unroll
            for (int p = 0; p < 8; p++) {
                u64 B2 = *(const u64*)&sB[t][2 * p];
                h2[p] = fma2(a2, h2[p], mul2(dtu2, B2));
                if (p < 7) a2 = mul2(a2, e22);
            }
        }
    } else {
        for (int t = 0; t < CH; t++) {
            float dt = __ldg(dtp + (size_t)t * DD);
            float uu = __ldg(up + (size_t)t * DD);
            sdt += dt;
            float dtu = dt * uu;
            u64 dtu2 = pk2(dtu, dtu);
#pragma unroll
            for (int p = 0; p < 8; p++) {
                u64 a2 = pk2(__expf(dt * Av[2 * p]), __expf(dt * Av[2 * p + 1]));
                u64 B2 = *(const u64*)&sB[t][2 * p];
                h2[p] = fma2(a2, h2[p], mul2(dtu2, B2));
            }
        }
    }

    u64* hf = (u64*)(g_hf + ((size_t)((b * NCH + c) * DD) + d) * NN);
#pragma unroll
    for (int p = 0; p < 8; p++) hf[p] = h2[p];
    g_sdt[(b * NCH + c) * DD + d] = sdt;
}

// ================= Scan phase B: inter-chunk recurrence (two-half preload) =================
__global__ void __launch_bounds__(256) k_scanB(const float* __restrict__ A_log) {
    const int gid = blockIdx.x * 256 + threadIdx.x;  // < B*D*N = 65536
    const int b = gid >> 15;
    const int rem = gid & 32767;
    const int d = rem >> 4;
    const int n = rem & 15;
    const float A = -__expf(A_log[d * 16 + n]);

    float h = 0.f;
#pragma unroll
    for (int half = 0; half < 2; half++) {
        float av[32], fv[32];
#pragma unroll
        for (int i = 0; i < 32; i++) {
            int base = (b * NCH + half * 32 + i) * DD + d;
            av[i] = g_sdt[base];
            fv[i] = g_hf[(size_t)base * NN + n];
        }
#pragma unroll
        for (int i = 0; i < 32; i++) av[i] = __expf(A * av[i]);
#pragma unroll
        for (int i = 0; i < 32; i++) {
            int base = (b * NCH + half * 32 + i) * DD + d;
            g_h0[(size_t)base * NN + n] = h;
            h = fmaf(av[i], h, fv[i]);
        }
    }
}

// ================= Scan phase C: re-scan with correct h0, emit y =================
__global__ void __launch_bounds__(256) k_scanC(const float* __restrict__ u,
                                               const float* __restrict__ A_log,
                                               const float* __restrict__ Dv,
                                               float* __restrict__ out) {
    __shared__ __align__(16) float sBC[CH][32];
    const int b = blockIdx.z, c = blockIdx.y;
    const int tid = threadIdx.x;
    const int d = blockIdx.x * 256 + tid;
    const int l0 = c * CH;

#pragma unroll
    for (int p = 0; p < 4; p++) {
        int idx = tid + p * 256;
        int t = idx >> 5, j = idx & 31;
        sBC[t][j] = g_xdbl[(b * LL + l0 + t) * KX + 64 + j];
    }
    __syncthreads();

    float Av[16];
    const bool powok = load_A(A_log, d, Av);
    const float Dd = Dv[d];

    u64 h2[8];
    {
        const u64* h0p = (const u64*)(g_h0 + ((size_t)((b * NCH + c) * DD) + d) * NN);
#pragma unroll
        for (int p = 0; p < 8; p++) h2[p] = h0p[p];
    }

    const size_t base0 = (size_t)(b * LL + l0) * DD + d;
    const float* dtp = g_dt + base0;
    const float* up = u + base0;
    float* yp = out + base0;

    if (powok) {
        const float A0 = Av[0];
#pragma unroll 2
        for (int t = 0; t < CH; t++) {
            float dt = __ldg(dtp + (size_t)t * DD);
            float uu = __ldg(up + (size_t)t * DD);
            float e1 = __expf(A0 * dt);
            float e2 = e1 * e1;
            u64 a2 = pk2(e1, e2);
            u64 e22 = pk2(e2, e2);
            float dtu = dt * uu;
            u64 dtu2 = pk2(dtu, dtu);
            u64 y2 = 0ull;
#pragma unroll
            for (int p = 0; p < 8; p++) {
                u64 B2 = *(const u64*)&sBC[t][2 * p];
                u64 C2 = *(const u64*)&sBC[t][16 + 2 * p];
                h2[p] = fma2(a2, h2[p], mul2(dtu2, B2));
                y2 = fma2(h2[p], C2, y2);
                if (p < 7) a2 = mul2(a2, e22);
            }
            float ylo, yhi; unpk2(y2, ylo, yhi);
            yp[(size_t)t * DD] = fmaf(uu, Dd, ylo + yhi);
        }
    } else {
        for (int t = 0; t < CH; t++) {
            float dt = __ldg(dtp + (size_t)t * DD);
            float uu = __ldg(up + (size_t)t * DD);
            float dtu = dt * uu;
            u64 dtu2 = pk2(dtu, dtu);
            u64 y2 = 0ull;
#pragma unroll
            for (int p = 0; p < 8; p++) {
                u64 a2 = pk2(__expf(dt * Av[2 * p]), __expf(dt * Av[2 * p + 1]));
                u64 B2 = *(const u64*)&sBC[t][2 * p];
                u64 C2 = *(const u64*)&sBC[t][16 + 2 * p];
                h2[p] = fma2(a2, h2[p], mul2(dtu2, B2));
                y2 = fma2(h2[p], C2, y2);
            }
            float ylo, yhi; unpk2(y2, ylo, yhi);
            yp[(size_t)t * DD] = fmaf(uu, Dd, ylo + yhi);
        }
    }
}

// ================= launch =================
extern "C" void kernel_launch(void* const* d_in, const int* in_sizes, int n_in,
                              void* d_out, int out_size) {
    const float* u     = (const float*)d_in[0];
    const float* A_log = (const float*)d_in[1];
    const float* Dv    = (const float*)d_in[2];
    const float* Wx    = (const float*)d_in[3];
    const float* Wdt   = (const float*)d_in[4];
    const float* bdt   = (const float*)d_in[5];
    float* out = (float*)d_out;

    k_gemm1<<<dim3(64, 8), 256>>>(u, Wx);
    k_red1<<<384, 256>>>();
    k_gemm2<<<dim3(64, 16), 256>>>(Wdt, bdt);
    k_scanA<<<dim3(DD / 256, NCH, BB), 256>>>(u, A_log);
    k_scanB<<<(BB * DD * NN) / 256, 256>>>(A_log);
    k_scanC<<<dim3(DD / 256, NCH, BB), 256>>>(u, A_log, Dv, out);
}